// round 4
// baseline (speedup 1.0000x reference)
#include <cuda_runtime.h>
#include <float.h>

// Fused sRGB->CIELab + per-image L min-max normalization, two-kernel version.
// K1: per-image Y min/max (L monotonic in Y). 4 CTAs/image -> partials.
// K2: full Lab + normalization; reads input from L2 residue (K1 warmed it),
//     output written with streaming stores (__stcs) so writes don't evict
//     the input from L2. All 32-bit indexing.

#define NPIX      16384            // 128*128
#define NIMG      512
#define K1_SUBS   4
#define K2_SUBS   8
#define THREADS   256
#define K1_PX     (NPIX / K1_SUBS)         // 4096
#define K2_PX     (NPIX / K2_SUBS)         // 2048
#define K1_GROUPS (K1_PX / (THREADS * 4))  // 4
#define K2_GROUPS (K2_PX / (THREADS * 4))  // 2

__device__ float g_pmin[NIMG * K1_SUBS];
__device__ float g_pmax[NIMG * K1_SUBS];

__device__ __forceinline__ float mufu_lg2(float x) {
    float r; asm("lg2.approx.f32 %0, %1;" : "=f"(r) : "f"(x)); return r;
}
__device__ __forceinline__ float mufu_ex2(float x) {
    float r; asm("ex2.approx.f32 %0, %1;" : "=f"(r) : "f"(x)); return r;
}
__device__ __forceinline__ float mufu_rcp(float x) {
    float r; asm("rcp.approx.f32 %0, %1;" : "=f"(r) : "f"(x)); return r;
}

__device__ __forceinline__ float srgb_lin(float c) {
    float t = fmaf(c, 1.0f / 1.055f, 0.055f / 1.055f);
    float p = mufu_ex2(2.4f * mufu_lg2(t));
    return (c > 0.04045f) ? p : c * (1.0f / 12.92f);
}

__device__ __forceinline__ float xyz_f(float t) {
    float cr = mufu_ex2((1.0f / 3.0f) * mufu_lg2(t));
    return (t > 0.008856f) ? cr : fmaf(t, 7.787f, 16.0f / 116.0f);
}

__device__ __forceinline__ float lum_Y(float r, float g, float b) {
    float rl = srgb_lin(r), gl = srgb_lin(g), bl = srgb_lin(b);
    return fmaf(0.212671f, rl, fmaf(0.715160f, gl, 0.072169f * bl));
}

// ---------------------------------------------------------------- K1
__global__ void __launch_bounds__(THREADS)
minmax_kernel(const float* __restrict__ x) {
    __shared__ float red[16];
    const int bid = blockIdx.x;
    const int tid = threadIdx.x;

    // base in float4 units: bid * (K1_PX*3/4) = bid * 3072  (fits int easily)
    const float4* in4 = (const float4*)x + bid * (K1_PX * 3 / 4);

    // 4 independent accumulator pairs to break the fmin/fmax dep chain
    float mn0 = FLT_MAX, mn1 = FLT_MAX, mn2 = FLT_MAX, mn3 = FLT_MAX;
    float mx0 = -FLT_MAX, mx1 = -FLT_MAX, mx2 = -FLT_MAX, mx3 = -FLT_MAX;

    #pragma unroll
    for (int j = 0; j < K1_GROUPS; j++) {
        int gi = tid + j * THREADS;
        float4 v0 = in4[gi * 3 + 0];
        float4 v1 = in4[gi * 3 + 1];
        float4 v2 = in4[gi * 3 + 2];
        float y0 = lum_Y(v0.x, v0.y, v0.z);
        float y1 = lum_Y(v0.w, v1.x, v1.y);
        float y2 = lum_Y(v1.z, v1.w, v2.x);
        float y3 = lum_Y(v2.y, v2.z, v2.w);
        mn0 = fminf(mn0, y0); mx0 = fmaxf(mx0, y0);
        mn1 = fminf(mn1, y1); mx1 = fmaxf(mx1, y1);
        mn2 = fminf(mn2, y2); mx2 = fmaxf(mx2, y2);
        mn3 = fminf(mn3, y3); mx3 = fmaxf(mx3, y3);
    }
    float ymin = fminf(fminf(mn0, mn1), fminf(mn2, mn3));
    float ymax = fmaxf(fmaxf(mx0, mx1), fmaxf(mx2, mx3));

    #pragma unroll
    for (int off = 16; off > 0; off >>= 1) {
        ymin = fminf(ymin, __shfl_xor_sync(0xffffffffu, ymin, off));
        ymax = fmaxf(ymax, __shfl_xor_sync(0xffffffffu, ymax, off));
    }
    int lane = tid & 31, wid = tid >> 5;
    if (lane == 0) { red[wid] = ymin; red[8 + wid] = ymax; }
    __syncthreads();
    if (tid == 0) {
        float mn = red[0], mx = red[8];
        #pragma unroll
        for (int i = 1; i < 8; i++) {
            mn = fminf(mn, red[i]);
            mx = fmaxf(mx, red[8 + i]);
        }
        g_pmin[bid] = mn;
        g_pmax[bid] = mx;
    }
}

// ---------------------------------------------------------------- K2
__device__ __forceinline__ void lab_pixel(float r, float g, float b,
                                          float fmin, float sf,
                                          float& L01, float& a01, float& b01) {
    float rl = srgb_lin(r);
    float gl = srgb_lin(g);
    float bl = srgb_lin(b);
    const float M00 = 0.412453f / 0.95047f, M01 = 0.357580f / 0.95047f, M02 = 0.180423f / 0.95047f;
    const float M10 = 0.212671f,            M11 = 0.715160f,            M12 = 0.072169f;
    const float M20 = 0.019334f / 1.08883f, M21 = 0.119193f / 1.08883f, M22 = 0.950227f / 1.08883f;
    float X = fmaf(M00, rl, fmaf(M01, gl, M02 * bl));
    float Y = fmaf(M10, rl, fmaf(M11, gl, M12 * bl));
    float Z = fmaf(M20, rl, fmaf(M21, gl, M22 * bl));
    float fx = xyz_f(X);
    float fy = xyz_f(Y);
    float fz = xyz_f(Z);
    L01 = (fy - fmin) * sf;
    a01 = fmaf(fx - fy, 500.0f / 255.0f, 128.0f / 255.0f);
    b01 = fmaf(fy - fz, 200.0f / 255.0f, 128.0f / 255.0f);
}

__global__ void __launch_bounds__(THREADS)
convert_kernel(const float* __restrict__ x, float* __restrict__ out) {
    const int bid = blockIdx.x;
    const int img = (NIMG - 1) - (bid >> 3);   // reverse order for L2 reuse
    const int sub = bid & 7;
    const int tid = threadIdx.x;

    float ymn = fminf(fminf(g_pmin[img * 4 + 0], g_pmin[img * 4 + 1]),
                      fminf(g_pmin[img * 4 + 2], g_pmin[img * 4 + 3]));
    float ymx = fmaxf(fmaxf(g_pmax[img * 4 + 0], g_pmax[img * 4 + 1]),
                      fmaxf(g_pmax[img * 4 + 2], g_pmax[img * 4 + 3]));
    float fmin = xyz_f(ymn);
    float fmax = xyz_f(ymx);
    float sf = mufu_rcp(fmax - fmin);

    // base in float4 units: img*12288 + sub*1536  (max ~6.3M, fits int)
    const int base4 = img * (NPIX * 3 / 4) + sub * (K2_PX * 3 / 4);
    const float4* in4 = (const float4*)x   + base4;
    float4*       o4  = (float4*)      out + base4;

    #pragma unroll
    for (int j = 0; j < K2_GROUPS; j++) {
        int gi = tid + j * THREADS;
        float4 v0 = in4[gi * 3 + 0];
        float4 v1 = in4[gi * 3 + 1];
        float4 v2 = in4[gi * 3 + 2];

        float L0, a0, b0, L1, a1, b1, L2, a2, b2, L3, a3, b3;
        lab_pixel(v0.x, v0.y, v0.z, fmin, sf, L0, a0, b0);
        lab_pixel(v0.w, v1.x, v1.y, fmin, sf, L1, a1, b1);
        lab_pixel(v1.z, v1.w, v2.x, fmin, sf, L2, a2, b2);
        lab_pixel(v2.y, v2.z, v2.w, fmin, sf, L3, a3, b3);

        // streaming stores: don't pollute L2 (keep input resident)
        __stcs(&o4[gi * 3 + 0], make_float4(L0, a0, b0, L1));
        __stcs(&o4[gi * 3 + 1], make_float4(a1, b1, L2, a2));
        __stcs(&o4[gi * 3 + 2], make_float4(b2, L3, a3, b3));
    }
}

extern "C" void kernel_launch(void* const* d_in, const int* in_sizes, int n_in,
                              void* d_out, int out_size) {
    const float* x   = (const float*)d_in[0];
    float*       out = (float*)d_out;

    minmax_kernel <<<NIMG * K1_SUBS, THREADS>>>(x);
    convert_kernel<<<NIMG * K2_SUBS, THREADS>>>(x, out);
}